// round 17
// baseline (speedup 1.0000x reference)
#include <cuda_runtime.h>
#include <float.h>
#include <stdint.h>

// STCA loss — fused kernel, integer bitmask spike scan, DENSE BLOCK-BURST loads.
//  r17: burst-granularity endgame. Block = 8 whole traces = ONE contiguous 64KB
//  gmem region. Warp w owns 2 traces (16KB contiguous) and fills its smem with
//  32 LDGSTS, each instruction covering 512B CONTIGUOUS (max DRAM/L1 density;
//  r16's L2::256B hint was the only lever in 5 rounds that moved the ~5.1TB/s
//  plateau -> push burst size to the structural limit). No ring: load-all ->
//  wait -> scan; latency hidden across 3 resident blocks/SM + CLC replacement.
//  Thread (trace = tid>>4, chunk = tid&15) scans 128 steps (4 mask words).
//  PITCH 132 words (528B rows): LDS.128 conflict-free. Integer-only monoid;
//  winning cluster's positive mean recomputed deferred; vmax lazy.
// Output: d_out[0] = loss, d_out[1 + trace] = num_clusters as float.

#define B_DIM 128
#define N_DIM 256
#define T_DIM 2048
#define C_GAP 3
#define NTRACE (B_DIM * N_DIM)        // 32768

#define S_CHUNKS 16
#define CHUNK_T  (T_DIM / S_CHUNKS)   // 128 steps = 512B per thread
#define TR_PB    8                    // traces per block (64KB contiguous)
#define TPB      (TR_PB * S_CHUNKS)   // 128 threads
#define PITCHW   132                  // words per smem row (528B; conflict-free)
#define SMEM_BYTES (TPB * PITCHW * 4) // 67584 B -> 3 blocks/SM
#define NBLOCKS  (NTRACE / TR_PB)     // 4096

#define SENT (1 << 30)

__device__ float        g_partial[NBLOCKS];
__device__ unsigned int g_count;      // zero-init; reset each replay by last block

__device__ __forceinline__ void cp_async16(uint32_t saddr, const float* gptr) {
    asm volatile("cp.async.cg.shared.global.L2::256B [%0], [%1], 16;\n"
                 :: "r"(saddr), "l"(gptr));
}
__device__ __forceinline__ void cp_commit() { asm volatile("cp.async.commit_group;\n"); }
template <int N>
__device__ __forceinline__ void cp_wait() { asm volatile("cp.async.wait_group %0;\n" :: "n"(N)); }

__global__ void __launch_bounds__(TPB, 3)
stca_fused(const float* __restrict__ vmem,
           const int*   __restrict__ labels,
           float*       __restrict__ out)
{
    extern __shared__ float sm[];
    __shared__ bool amLast;

    const int tid       = threadIdx.x;
    const int traceBase = blockIdx.x * TR_PB;
    const int tr        = tid >> 4;        // trace 0..7
    const int c         = tid & 15;        // chunk 0..15
    const int wid       = tid >> 5;        // warp owns traces 2w, 2w+1 (16KB contig)
    const int lane      = tid & 31;

    // ---- dense load: warp region = 16KB contiguous; instruction k fills
    //      warp-row k (= thread 32w+k's 512B chunk), lanes cover 512B contig ----
    {
        const float*   gwarp = vmem + (size_t)(traceBase + 2 * wid) * T_DIM;
        const uint32_t swarp = (uint32_t)__cvta_generic_to_shared(sm)
                             + (uint32_t)(32 * wid) * (PITCHW * 4);
        #pragma unroll
        for (int kk = 0; kk < 32; kk++) {
            cp_async16(swarp + kk * (PITCHW * 4) + lane * 16,
                       gwarp + kk * 128 + lane * 4);
        }
        cp_commit();
    }
    cp_wait<0>();
    __syncwarp();

    // ---- scan my 128-step chunk (4 x 32-bit mask words), integer monoid ----
    int last  = -1000000;                  // global time of previous spike
    int k = 0, ft = -1;
    int curc = 0, curst = 0;               // open cluster: count, start time
    int Fc = 0,    Fst = 0, Fen = 0;       // first cluster (count, start, end)
    int Ic = SENT, Ist = 0, Ien = 0;       // best interior cluster

    const float* myrow = sm + tid * PITCHW;
    const int gchunk = c * CHUNK_T;        // global time base of my chunk

    #pragma unroll
    for (int w4 = 0; w4 < 4; w4++) {
        const float* r = myrow + w4 * 32;

        uint32_t nm = 0;
        #pragma unroll
        for (int j = 0; j < 8; j++) {
            const uint4 u = *reinterpret_cast<const uint4*>(r + 4 * j);
            uint32_t t0 = __byte_perm(u.x, u.y, 0x0073);
            uint32_t t1 = __byte_perm(u.z, u.w, 0x0073);
            uint32_t sb = __byte_perm(t0, t1, 0x5410);
            sb &= 0x80808080u;
            nm |= ((sb * 0x00204081u) >> 28) << (4 * j);
        }
        uint32_t m = ~nm;                  // spike mask (v >= 0)

        if (m) {
            const int wb = gchunk + w4 * 32;
            if (ft < 0) ft = wb + __ffs(m) - 1;
            do {
                const int i = __ffs(m) - 1;
                m &= m - 1;
                const int  tg = wb + i;
                const bool nw = (tg - last) > C_GAP;
                const bool cF = nw && (k == 1);
                const bool cI = nw && (k >= 2) && (curc < Ic);
                Fc = cF ? curc : Fc;  Fst = cF ? curst : Fst;  Fen = cF ? last : Fen;
                Ic = cI ? curc : Ic;  Ist = cI ? curst : Ist;  Ien = cI ? last : Ien;
                k += nw;
                curst = nw ? tg : curst;
                curc  = (nw ? 0 : curc) + 1;
                last  = tg;
            } while (m);
        }
    }

    if (k == 1) { Fc = curc; Fst = curst; Fen = last; }
    // open/last cluster L = (curc, curst, last)

    // Lazy vmax: only when the chunk has NO spikes. Rescan gmem.
    float vmax = -FLT_MAX;
    if (k == 0) {
        const float* g = vmem + (size_t)(traceBase + tr) * T_DIM + gchunk;
        #pragma unroll 1
        for (int j = 0; j < CHUNK_T; j++) vmax = fmaxf(vmax, g[j]);
    }

    // ---- chunk summaries to smem: row = tid = tr*16 + c ----
    __syncthreads();
    float* summ = sm;
    {
        float* w = summ + tid * 16;
        w[0]  = vmax;
        w[1]  = (float)ft;                 // -1 if no spike (k==0)
        w[2]  = (float)last;               // valid iff k>0
        w[3]  = (float)k;
        w[4]  = (float)Fc;   w[5]  = (float)Fst;  w[6]  = (float)Fen;
        w[7]  = (float)Ic;   w[8]  = (float)Ist;  w[9]  = (float)Ien;
        w[10] = (float)curc; w[11] = (float)curst; w[12] = (float)last;
    }
    __syncthreads();

    // ---- merge 16 chunk summaries per trace (threads 0..7) ----
    float* red = sm + TPB * 16;
    float contrib = 0.0f;
    if (tid < TR_PB) {
        float vx = -FLT_MAX;
        int last_t = -1000000, nclust = 0;
        int opc = -1, opst = 0;                      // open cluster (count, start)
        int bc = SENT, bst = 0, ben = 0;             // best closed (count, span)
        #pragma unroll
        for (int cc = 0; cc < S_CHUNKS; cc++) {
            const float* w = summ + (tid * S_CHUNKS + cc) * 16;
            vx = fmaxf(vx, w[0]);
            const int kk = (int)w[3];
            if (kk == 0) continue;
            const int ftc = (int)w[1], ltc = (int)w[2];
            const int fC = (int)w[4],  fS = (int)w[5],  fE = (int)w[6];
            const int iC = (int)w[7],  iS = (int)w[8],  iE = (int)w[9];
            const int lC = (int)w[10], lS = (int)w[11];

            if (opc >= 0 && (ftc - last_t) <= C_GAP) {
                const int mc = opc + fC;             // merged: span (opst, fE)
                if (kk == 1) { opc = mc; }
                else {
                    if (mc < bc) { bc = mc; bst = opst; ben = fE; }
                    if (iC < bc) { bc = iC; bst = iS;   ben = iE; }
                    opc = lC; opst = lS;
                    nclust += kk - 1;
                }
            } else {
                if (opc >= 0 && opc < bc) { bc = opc; bst = opst; ben = last_t; }
                nclust += kk;
                if (kk == 1) { opc = fC; opst = fS; }
                else {
                    if (fC < bc) { bc = fC; bst = fS; ben = fE; }
                    if (iC < bc) { bc = iC; bst = iS; ben = iE; }
                    opc = lC; opst = lS;
                }
            }
            last_t = ltc;
        }
        if (opc >= 0 && opc < bc) { bc = opc; bst = opst; ben = last_t; }

        const int trace = traceBase + tid;
        out[1 + trace] = (float)nclust;

        const int b = trace / N_DIM;
        const int n = trace - b * N_DIM;
        if (n == labels[b]) {
            if (nclust == 0) contrib = -vx;
        } else if (nclust > 0) {
            // Deferred: mean of v>0 over the winning cluster's span (ascending t).
            const float* g = vmem + (size_t)trace * T_DIM;
            float s = 0.0f; int pc = 0;
            #pragma unroll 1
            for (int t = bst; t <= ben; t++) {
                const float v = g[t];
                if (v > 0.0f) { s += v; pc++; }
            }
            contrib = s / fmaxf((float)pc, 1.0f);
        }
    }

    // ---- block tree reduction (128 threads; >=8 contribute 0) ----
    red[tid] = contrib;
    __syncthreads();
    #pragma unroll
    for (int off = TPB / 2; off > 0; off >>= 1) {
        if (tid < off) red[tid] += red[tid + off];
        __syncthreads();
    }
    if (tid == 0) {
        g_partial[blockIdx.x] = red[0];
        __threadfence();
        amLast = (atomicAdd(&g_count, 1u) == (unsigned)(gridDim.x - 1));
    }
    __syncthreads();

    if (amLast) {
        __threadfence();
        float x = 0.0f;
        #pragma unroll
        for (int j = 0; j < NBLOCKS / TPB; j++) x += g_partial[tid + TPB * j];
        red[tid] = x;
        __syncthreads();
        #pragma unroll
        for (int off = TPB / 2; off > 0; off >>= 1) {
            if (tid < off) red[tid] += red[tid + off];
            __syncthreads();
        }
        if (tid == 0) {
            out[0] = red[0];
            g_count = 0;                   // reset for next graph replay
        }
    }
}

extern "C" void kernel_launch(void* const* d_in, const int* in_sizes, int n_in,
                              void* d_out, int out_size)
{
    const float* vmem   = (const float*)d_in[0];
    // d_in[1] (vlastmem) unused by the forward computation.
    const int*   labels = (const int*)d_in[2];
    float*       out    = (float*)d_out;

    cudaFuncSetAttribute(stca_fused, cudaFuncAttributeMaxDynamicSharedMemorySize, SMEM_BYTES);
    stca_fused<<<NBLOCKS, TPB, SMEM_BYTES>>>(vmem, labels, out);
}